// round 13
// baseline (speedup 1.0000x reference)
#include <cuda_runtime.h>
#include <math.h>
#include <stdint.h>

#define BROWS 8192
#define DIM   256
#define RSB   272               // smem row stride bytes (256 int8 + 16 pad)
#define ATILE (128 * RSB)       // 34816 B per tile slot
#define NCTA  148
#define NTHR  512
#define QS    360.0f

static __device__ __constant__ float kEPS = 1e-8f;

// ------------------------- device scratch ----------------------------------
__device__ __align__(16) signed char g_xq[BROWS * DIM];  // int8 normalized (2 MB)
__device__ float                     g_inv[BROWS];       // per-row 1/norm
__device__ unsigned long long        g_best[BROWS];

// ------------------------- helpers -----------------------------------------
__device__ __forceinline__ uint32_t smem_u32(const void* p) {
    uint32_t a;
    asm("{ .reg .u64 t; cvta.to.shared.u64 t, %1; cvt.u32.u64 %0, t; }" : "=r"(a) : "l"(p));
    return a;
}
__device__ __forceinline__ void ldsm4(uint32_t r[4], uint32_t a) {
    asm volatile("ldmatrix.sync.aligned.m8n8.x4.shared.b16 {%0,%1,%2,%3}, [%4];"
                 : "=r"(r[0]), "=r"(r[1]), "=r"(r[2]), "=r"(r[3]) : "r"(a));
}
// INT8 MMA: m16n8k32, s32 accumulate
__device__ __forceinline__ void mma16832i(int c[4], const uint32_t a[4],
                                          uint32_t b0, uint32_t b1) {
    asm volatile("mma.sync.aligned.m16n8k32.row.col.s32.s8.s8.s32 "
                 "{%0,%1,%2,%3}, {%4,%5,%6,%7}, {%8,%9}, {%0,%1,%2,%3};"
                 : "+r"(c[0]), "+r"(c[1]), "+r"(c[2]), "+r"(c[3])
                 : "r"(a[0]), "r"(a[1]), "r"(a[2]), "r"(a[3]), "r"(b0), "r"(b1));
}
#define CP16(dst, src)  asm volatile("cp.async.cg.shared.global [%0], [%1], 16;" :: "r"(dst), "l"(src) : "memory")
#define CPCOMMIT()      asm volatile("cp.async.commit_group;" ::: "memory")
#define CPWAIT0()       asm volatile("cp.async.wait_group 0;" ::: "memory")

// pack: high 32 = biased int sum (monotone), low 32 = 8191-idx (tie -> smaller idx)
__device__ __forceinline__ unsigned long long pack_iv(int v, int idx) {
    return ((unsigned long long)(unsigned)(v + 0x40000000) << 32) |
           (unsigned)(8191 - idx);
}
__device__ __forceinline__ int unpack_idx(unsigned long long p) {
    return 8191 - (int)(p & 0xFFFFFFFFull);
}
__device__ __forceinline__ unsigned long long u64max(unsigned long long a,
                                                     unsigned long long b) {
    return a > b ? a : b;
}
__device__ __forceinline__ unsigned long long shfl_xor_u64(unsigned long long v, int m) {
    uint32_t lo = (uint32_t)v, hi = (uint32_t)(v >> 32);
    lo = __shfl_xor_sync(0xffffffffu, lo, m);
    hi = __shfl_xor_sync(0xffffffffu, hi, m);
    return ((unsigned long long)hi << 32) | lo;
}
__device__ __forceinline__ int q8(float v) {
    int q = __float2int_rn(v * QS);
    return q < -127 ? -127 : (q > 127 ? 127 : q);
}

// ---------------------------------------------------------------------------
// Kernel 1: normalize -> int8 + inv-norm; zero g_best; zero out. 1 warp/row.
__global__ void koleo_normcvt(const float* __restrict__ x, float* __restrict__ out) {
    int row  = blockIdx.x * 8 + (threadIdx.x >> 5);
    int lane = threadIdx.x & 31;
    const float4* src = (const float4*)(x + (size_t)row * DIM);
    float4 v0 = src[lane];
    float4 v1 = src[lane + 32];
    float s = v0.x*v0.x + v0.y*v0.y + v0.z*v0.z + v0.w*v0.w
            + v1.x*v1.x + v1.y*v1.y + v1.z*v1.z + v1.w*v1.w;
    #pragma unroll
    for (int o = 16; o > 0; o >>= 1) s += __shfl_xor_sync(0xffffffffu, s, o);
    float inv = 1.0f / fmaxf(sqrtf(s), kEPS);

    int q0 = q8(v0.x * inv), q1 = q8(v0.y * inv), q2 = q8(v0.z * inv), q3 = q8(v0.w * inv);
    uint32_t w0 = (uint32_t)(q0 & 255) | ((uint32_t)(q1 & 255) << 8) |
                  ((uint32_t)(q2 & 255) << 16) | ((uint32_t)(q3 & 255) << 24);
    q0 = q8(v1.x * inv); q1 = q8(v1.y * inv); q2 = q8(v1.z * inv); q3 = q8(v1.w * inv);
    uint32_t w1 = (uint32_t)(q0 & 255) | ((uint32_t)(q1 & 255) << 8) |
                  ((uint32_t)(q2 & 255) << 16) | ((uint32_t)(q3 & 255) << 24);
    uint32_t* dst = (uint32_t*)(g_xq + (size_t)row * DIM);
    dst[lane] = w0;
    dst[lane + 32] = w1;
    if (lane == 0) { g_inv[row] = inv; g_best[row] = 0ull; }
    if (blockIdx.x == 0 && threadIdx.x == 0) out[0] = 0.0f;
}

// ---------------------------------------------------------------------------
// 32x32 warp tile, int8/s32. 8 k-steps of 32 bytes; prefetch 1 chunk/thread
// at k=2..5 (4 chunks total = full next tile across 512 threads).
__device__ __forceinline__ void mma_tile(int (&c_)[2][4][4], uint32_t uA, uint32_t uB,
                                         uint32_t aoff, uint32_t boff,
                                         bool pf, uint32_t pfdst,
                                         const signed char* __restrict__ pfsrc, int tid) {
    #pragma unroll
    for (int mi = 0; mi < 2; mi++)
        #pragma unroll
        for (int ni = 0; ni < 4; ni++)
            #pragma unroll
            for (int q = 0; q < 4; q++) c_[mi][ni][q] = 0;
    #pragma unroll
    for (int k = 0; k < 8; k++) {
        if (k >= 2 && k < 6 && pf) {
            int flat = tid + (k - 2) * NTHR;       // 0..2047
            int r = flat >> 4;                     // row 0..127
            int c = flat & 15;                     // 16B chunk
            CP16(pfdst + r * RSB + c * 16, pfsrc + (size_t)r * DIM + c * 16);
        }
        uint32_t a0[4], a1[4];
        ldsm4(a0, uA + aoff + k * 32);
        ldsm4(a1, uA + aoff + 16 * RSB + k * 32);
        uint32_t b[2][4];
        ldsm4(b[0], uB + boff + k * 32);
        ldsm4(b[1], uB + boff + 16 * RSB + k * 32);
        #pragma unroll
        for (int ni = 0; ni < 4; ni++) {
            uint32_t b0 = b[ni >> 1][(ni & 1) * 2];
            uint32_t b1 = b[ni >> 1][(ni & 1) * 2 + 1];
            mma16832i(c_[0][ni], a0, b0, b1);
            mma16832i(c_[1][ni], a1, b0, b1);
        }
    }
}

// fold tile: integer compares throughout; column-side via REDG u64 atomicMax.
__device__ __forceinline__ void fold_tile(const int (&c_)[2][4][4], int pi, int pj,
                                          int rloc, int wn, int l,
                                          int best[4], int bidx[4]) {
    const int colb = pj * 128 + wn * 32 + (l & 3) * 2;
    const int rbase = pi * 128 + rloc;
    if (pi == pj) {
        #pragma unroll
        for (int mi = 0; mi < 2; mi++)
            #pragma unroll
            for (int h = 0; h < 2; h++) {
                const int bi = mi * 2 + h;
                const int row = rbase + mi * 16 + h * 8;
                #pragma unroll
                for (int ni = 0; ni < 4; ni++)
                    #pragma unroll
                    for (int bb = 0; bb < 2; bb++) {
                        int v = c_[mi][ni][h * 2 + bb];
                        int col = colb + ni * 8 + bb;
                        if (col == row) continue;
                        if (v > best[bi]) { best[bi] = v; bidx[bi] = col; }
                    }
            }
    } else {
        #pragma unroll
        for (int mi = 0; mi < 2; mi++)
            #pragma unroll
            for (int h = 0; h < 2; h++) {
                const int bi = mi * 2 + h;
                #pragma unroll
                for (int ni = 0; ni < 4; ni++)
                    #pragma unroll
                    for (int bb = 0; bb < 2; bb++) {
                        int v = c_[mi][ni][h * 2 + bb];
                        int col = colb + ni * 8 + bb;
                        if (v > best[bi]) { best[bi] = v; bidx[bi] = col; }
                    }
            }
        // column fold: per (ni,bb), max over (mi,h), lanes xor 4/8/16, REDG
        #pragma unroll
        for (int ni = 0; ni < 4; ni++)
            #pragma unroll
            for (int bb = 0; bb < 2; bb++) {
                int bv = c_[0][ni][bb];        int br = rbase;
                int v;
                v = c_[0][ni][2 + bb]; if (v > bv) { bv = v; br = rbase + 8;  }
                v = c_[1][ni][bb];     if (v > bv) { bv = v; br = rbase + 16; }
                v = c_[1][ni][2 + bb]; if (v > bv) { bv = v; br = rbase + 24; }
                unsigned long long p = pack_iv(bv, br);
                p = u64max(p, shfl_xor_u64(p, 4));
                p = u64max(p, shfl_xor_u64(p, 8));
                p = u64max(p, shfl_xor_u64(p, 16));
                if ((l >> 2) == 0)
                    atomicMax(&g_best[colb + ni * 8 + bb], p);
            }
    }
}

__device__ __forceinline__ void flush_rows(int rowblk, int rloc, int l,
                                           int best[4], int bidx[4]) {
    #pragma unroll
    for (int bi = 0; bi < 4; bi++) {
        unsigned long long p = pack_iv(best[bi], bidx[bi]);
        p = u64max(p, shfl_xor_u64(p, 1));
        p = u64max(p, shfl_xor_u64(p, 2));
        if ((l & 3) == 0) {
            int row = rowblk * 128 + rloc + (bi >> 1) * 16 + (bi & 1) * 8;
            atomicMax(&g_best[row], p);
        }
        best[bi] = -0x40000000; bidx[bi] = 0;
    }
}

__device__ __forceinline__ int free_slot(int sa, int sb) {
    if (sa != 0 && sb != 0) return 0;
    if (sa != 1 && sb != 1) return 1;
    return 2;
}

// ---------------------------------------------------------------------------
// Kernel 2: persistent balanced upper-tri INT8 GEMM-argmax. 148 CTAs, 512 thr,
// 16 warps (4x4 grid of 32x32 warp tiles), 3 rotating smem slots.
__global__ void __launch_bounds__(NTHR, 1) koleo_gemm() {
    extern __shared__ __align__(16) char smem[];
    const uint32_t su = smem_u32(smem);
    const int tid = threadIdx.x;
    const int l   = tid & 31;
    const int wid = tid >> 5;
    const int wm  = wid >> 2;            // 0..3 (M)
    const int wn  = wid & 3;             // 0..3 (N)
    const int rloc = wm * 32 + (l >> 2);
    const int b   = blockIdx.x;

    const int cnt = 14 + (b < 8 ? 1 : 0);
    int s = b * 14 + (b < 8 ? b : 8);
    int i = 0;
    while (s >= 64 - i) { s -= 64 - i; i++; }
    int j = i + s;

    // fragment byte layout identical to fp16 case; RSB halved.
    const uint32_t aoff = (uint32_t)((wm * 32 + (l & 15)) * RSB + (l >> 4) * 16);
    const uint32_t boff = (uint32_t)((wn * 32 + (l & 7) + ((l >> 4) << 3)) * RSB +
                                     ((l >> 3) & 1) * 16);

    // initial loads: 2048 16B-chunks per tile, 4 per thread
    int sa = 0, sb;
    #pragma unroll
    for (int q = 0; q < 4; q++) {
        int flat = tid + q * NTHR;
        int r = flat >> 4;
        int c = flat & 15;
        CP16(su + r * RSB + c * 16,
             g_xq + (size_t)i * 128 * DIM + (size_t)r * DIM + c * 16);
    }
    if (j != i) {
        #pragma unroll
        for (int q = 0; q < 4; q++) {
            int flat = tid + q * NTHR;
            int r = flat >> 4;
            int c = flat & 15;
            CP16(su + ATILE + r * RSB + c * 16,
                 g_xq + (size_t)j * 128 * DIM + (size_t)r * DIM + c * 16);
        }
        sb = 1;
    } else sb = 0;
    CPCOMMIT();

    int best[4] = {-0x40000000, -0x40000000, -0x40000000, -0x40000000};
    int bidx[4] = {0, 0, 0, 0};
    int c_[2][4][4];

    #pragma unroll 1
    for (int n = 0; n < cnt; n++) {
        CPWAIT0();
        __syncthreads();

        int nsa = sa, nsb = sb, ii2 = i, jj2 = j;
        bool pf = (n + 1 < cnt);
        uint32_t pfdst = 0;
        const signed char* pfsrc = nullptr;
        if (pf) {
            int fs = free_slot(sa, sb);
            pfdst = su + fs * ATILE;
            if (j + 1 < 64) {
                pfsrc = g_xq + (size_t)(j + 1) * 128 * DIM;
                nsb = fs; jj2 = j + 1;
            } else {
                pfsrc = g_xq + (size_t)(i + 1) * 128 * DIM;
                nsa = fs; nsb = fs; ii2 = i + 1; jj2 = i + 1;
            }
        }

        mma_tile(c_, su + sa * ATILE, su + sb * ATILE, aoff, boff, pf, pfdst, pfsrc, tid);
        if (pf) CPCOMMIT();
        fold_tile(c_, i, j, rloc, wn, l, best, bidx);
        if (n + 1 == cnt || ii2 != i)
            flush_rows(i, rloc, l, best, bidx);

        sa = nsa; sb = nsb; i = ii2; j = jj2;
    }
}

// ---------------------------------------------------------------------------
// Kernel 3: per-row distance + log + fused reduction (exact fp32). 1 warp/row.
__global__ void koleo_dist(const float* __restrict__ x, float* __restrict__ out) {
    __shared__ float sh[8];
    int row  = blockIdx.x * 8 + (threadIdx.x >> 5);
    int lane = threadIdx.x & 31;
    int nb   = unpack_idx(g_best[row]);
    float ii = g_inv[row];
    float ij = g_inv[nb];
    const float4* xi = (const float4*)(x + (size_t)row * DIM);
    const float4* xj = (const float4*)(x + (size_t)nb  * DIM);
    float s = 0.0f;
    #pragma unroll
    for (int c = 0; c < 2; c++) {
        float4 a = xi[lane + c * 32];
        float4 b = xj[lane + c * 32];
        float d0 = a.x * ii - b.x * ij + kEPS, d1 = a.y * ii - b.y * ij + kEPS;
        float d2 = a.z * ii - b.z * ij + kEPS, d3 = a.w * ii - b.w * ij + kEPS;
        s = fmaf(d0, d0, s); s = fmaf(d1, d1, s);
        s = fmaf(d2, d2, s); s = fmaf(d3, d3, s);
    }
    #pragma unroll
    for (int o = 16; o > 0; o >>= 1) s += __shfl_xor_sync(0xffffffffu, s, o);
    if (lane == 0) sh[threadIdx.x >> 5] = logf(sqrtf(s) + kEPS);
    __syncthreads();
    if (threadIdx.x == 0) {
        float t = sh[0] + sh[1] + sh[2] + sh[3] + sh[4] + sh[5] + sh[6] + sh[7];
        atomicAdd(out, t * (-1.0f / (float)BROWS));
    }
}

// ---------------------------------------------------------------------------
extern "C" void kernel_launch(void* const* d_in, const int* in_sizes, int n_in,
                              void* d_out, int out_size) {
    const float* student = (const float*)d_in[0];
    float* out = (float*)d_out;
    (void)in_sizes; (void)n_in; (void)out_size;

    const int smem_bytes = 3 * ATILE;      // 104448 B dynamic
    cudaFuncSetAttribute(koleo_gemm, cudaFuncAttributeMaxDynamicSharedMemorySize, smem_bytes);

    koleo_normcvt<<<BROWS / 8, 256>>>(student, out);
    koleo_gemm<<<NCTA, NTHR, smem_bytes>>>();
    koleo_dist<<<BROWS / 8, 256>>>(student, out);
}

// round 14
// speedup vs baseline: 2.0808x; 2.0808x over previous
#include <cuda_runtime.h>
#include <cuda_fp16.h>
#include <math.h>
#include <stdint.h>

#define BROWS 8192
#define DIM   256
#define RSB   528           // smem row stride bytes (256 halves + 8 pad)
#define ATILE (128 * RSB)   // 67584 B per tile slot
#define NCTA  148
#define NTHR  512

static __device__ __constant__ float kEPS = 1e-8f;

// ------------------------- device scratch ----------------------------------
__device__ __align__(16) __half g_xh[BROWS * DIM];   // normalized fp16 (4 MB)
__device__ float                g_inv[BROWS];        // per-row 1/norm
__device__ unsigned long long   g_best[BROWS];

// ------------------------- helpers -----------------------------------------
__device__ __forceinline__ uint32_t smem_u32(const void* p) {
    uint32_t a;
    asm("{ .reg .u64 t; cvta.to.shared.u64 t, %1; cvt.u32.u64 %0, t; }" : "=r"(a) : "l"(p));
    return a;
}
__device__ __forceinline__ void ldsm4(uint32_t r[4], uint32_t a) {
    asm volatile("ldmatrix.sync.aligned.m8n8.x4.shared.b16 {%0,%1,%2,%3}, [%4];"
                 : "=r"(r[0]), "=r"(r[1]), "=r"(r[2]), "=r"(r[3]) : "r"(a));
}
__device__ __forceinline__ void mma16816h(uint32_t c[2], const uint32_t a[4],
                                          uint32_t b0, uint32_t b1) {
    asm volatile("mma.sync.aligned.m16n8k16.row.col.f16.f16.f16.f16 "
                 "{%0,%1}, {%2,%3,%4,%5}, {%6,%7}, {%0,%1};"
                 : "+r"(c[0]), "+r"(c[1])
                 : "r"(a[0]), "r"(a[1]), "r"(a[2]), "r"(a[3]), "r"(b0), "r"(b1));
}
#define CP16(dst, src)  asm volatile("cp.async.cg.shared.global [%0], [%1], 16;" :: "r"(dst), "l"(src) : "memory")
#define CPCOMMIT()      asm volatile("cp.async.commit_group;" ::: "memory")
#define CPWAIT0()       asm volatile("cp.async.wait_group 0;" ::: "memory")

// pack: high 32 = orderable key (dot+2 > 0), low 32 = 8191-idx (tie -> smaller idx)
__device__ __forceinline__ unsigned long long pack_vi(float v, int idx) {
    return ((unsigned long long)__float_as_uint(v + 2.0f) << 32) |
           (unsigned)(8191 - idx);
}
__device__ __forceinline__ int unpack_idx(unsigned long long p) {
    return 8191 - (int)(p & 0xFFFFFFFFull);
}
__device__ __forceinline__ unsigned long long u64max(unsigned long long a,
                                                     unsigned long long b) {
    return a > b ? a : b;
}
__device__ __forceinline__ unsigned long long shfl_xor_u64(unsigned long long v, int m) {
    uint32_t lo = (uint32_t)v, hi = (uint32_t)(v >> 32);
    lo = __shfl_xor_sync(0xffffffffu, lo, m);
    hi = __shfl_xor_sync(0xffffffffu, hi, m);
    return ((unsigned long long)hi << 32) | lo;
}

// ---------------------------------------------------------------------------
// Kernel 1: normalize -> fp16 + inv-norm; zero g_best; zero out. 1 warp/row.
__global__ void koleo_normcvt(const float* __restrict__ x, float* __restrict__ out) {
    int row  = blockIdx.x * 8 + (threadIdx.x >> 5);
    int lane = threadIdx.x & 31;
    const float4* src = (const float4*)(x + (size_t)row * DIM);
    float4 v0 = src[lane];
    float4 v1 = src[lane + 32];
    float s = v0.x*v0.x + v0.y*v0.y + v0.z*v0.z + v0.w*v0.w
            + v1.x*v1.x + v1.y*v1.y + v1.z*v1.z + v1.w*v1.w;
    #pragma unroll
    for (int o = 16; o > 0; o >>= 1) s += __shfl_xor_sync(0xffffffffu, s, o);
    float inv = 1.0f / fmaxf(sqrtf(s), kEPS);
    v0.x *= inv; v0.y *= inv; v0.z *= inv; v0.w *= inv;
    v1.x *= inv; v1.y *= inv; v1.z *= inv; v1.w *= inv;

    ushort4 H0, H1;
    H0.x = __half_as_ushort(__float2half_rn(v0.x));
    H0.y = __half_as_ushort(__float2half_rn(v0.y));
    H0.z = __half_as_ushort(__float2half_rn(v0.z));
    H0.w = __half_as_ushort(__float2half_rn(v0.w));
    H1.x = __half_as_ushort(__float2half_rn(v1.x));
    H1.y = __half_as_ushort(__float2half_rn(v1.y));
    H1.z = __half_as_ushort(__float2half_rn(v1.z));
    H1.w = __half_as_ushort(__float2half_rn(v1.w));
    ushort4* hdst = (ushort4*)(g_xh + (size_t)row * DIM);
    hdst[lane] = H0; hdst[lane + 32] = H1;
    if (lane == 0) { g_inv[row] = inv; g_best[row] = 0ull; }
    if (blockIdx.x == 0 && threadIdx.x == 0) out[0] = 0.0f;
}

// ---------------------------------------------------------------------------
// MMA of current tile into bank cc, with the FOLD OF THE PREVIOUS TILE
// (bank cp) interleaved at k=12..15 (one ni column-group per k-step) and the
// next-tile cp.async prefetch at k=4..11. The fold reads registers produced a
// full tile ago, so its instructions fill issue slots under HMMA latency.
__device__ __forceinline__ void mma_tile_fold(
    uint32_t (&cc)[2][4][2], const uint32_t (&cp)[2][4][2],
    uint32_t uA, uint32_t uB, uint32_t aoff, uint32_t boff,
    bool pf, uint32_t pfdst, const __half* __restrict__ pfsrc, int tid,
    bool dofold, int prbase, int pcolb, bool pdiag, int l,
    float best[4], int bidx[4]) {

    #pragma unroll
    for (int mi = 0; mi < 2; mi++)
        #pragma unroll
        for (int ni = 0; ni < 4; ni++) { cc[mi][ni][0] = 0u; cc[mi][ni][1] = 0u; }

    #pragma unroll
    for (int k = 0; k < 16; k++) {
        if (k >= 4 && k < 12 && pf) {
            int flat = tid + (k - 4) * NTHR;
            int r = flat >> 5;
            int c = flat & 31;
            CP16(pfdst + r * RSB + c * 16, pfsrc + (size_t)r * DIM + c * 8);
        }
        uint32_t a0[4], a1[4];
        ldsm4(a0, uA + aoff + k * 32);
        ldsm4(a1, uA + aoff + 16 * RSB + k * 32);
        uint32_t b[2][4];
        ldsm4(b[0], uB + boff + k * 32);
        ldsm4(b[1], uB + boff + 16 * RSB + k * 32);
        #pragma unroll
        for (int ni = 0; ni < 4; ni++) {
            uint32_t b0 = b[ni >> 1][(ni & 1) * 2];
            uint32_t b1 = b[ni >> 1][(ni & 1) * 2 + 1];
            mma16816h(cc[0][ni], a0, b0, b1);
            mma16816h(cc[1][ni], a1, b0, b1);
        }

        if (k >= 12 && dofold) {
            const int ni = k - 12;
            float f[2][4];
            {
                float2 lo = __half22float2(*(const __half2*)&cp[0][ni][0]);
                float2 hi = __half22float2(*(const __half2*)&cp[0][ni][1]);
                f[0][0] = lo.x; f[0][1] = lo.y; f[0][2] = hi.x; f[0][3] = hi.y;
                lo = __half22float2(*(const __half2*)&cp[1][ni][0]);
                hi = __half22float2(*(const __half2*)&cp[1][ni][1]);
                f[1][0] = lo.x; f[1][1] = lo.y; f[1][2] = hi.x; f[1][3] = hi.y;
            }
            if (pdiag) {
                #pragma unroll
                for (int mi = 0; mi < 2; mi++)
                    #pragma unroll
                    for (int h = 0; h < 2; h++) {
                        const int bi = mi * 2 + h;
                        const int row = prbase + mi * 16 + h * 8;
                        #pragma unroll
                        for (int bb = 0; bb < 2; bb++) {
                            float v = f[mi][h * 2 + bb];
                            int col = pcolb + ni * 8 + bb;
                            if (col != row && v > best[bi]) { best[bi] = v; bidx[bi] = col; }
                        }
                    }
            } else {
                #pragma unroll
                for (int mi = 0; mi < 2; mi++)
                    #pragma unroll
                    for (int h = 0; h < 2; h++) {
                        const int bi = mi * 2 + h;
                        #pragma unroll
                        for (int bb = 0; bb < 2; bb++) {
                            float v = f[mi][h * 2 + bb];
                            int col = pcolb + ni * 8 + bb;
                            if (v > best[bi]) { best[bi] = v; bidx[bi] = col; }
                        }
                    }
                #pragma unroll
                for (int bb = 0; bb < 2; bb++) {
                    float bv = f[0][bb];       int br = prbase;
                    float v;
                    v = f[0][2 + bb]; if (v > bv) { bv = v; br = prbase + 8;  }
                    v = f[1][bb];     if (v > bv) { bv = v; br = prbase + 16; }
                    v = f[1][2 + bb]; if (v > bv) { bv = v; br = prbase + 24; }
                    unsigned long long p = pack_vi(bv, br);
                    p = u64max(p, shfl_xor_u64(p, 4));
                    p = u64max(p, shfl_xor_u64(p, 8));
                    p = u64max(p, shfl_xor_u64(p, 16));
                    if ((l >> 2) == 0)
                        atomicMax(&g_best[pcolb + ni * 8 + bb], p);
                }
            }
        }
    }
}

// standalone fold (for the last tile, outside the pipeline)
__device__ __forceinline__ void fold_tile(const uint32_t (&c_)[2][4][2],
                                          int rbase, int colb, bool diag, int l,
                                          float best[4], int bidx[4]) {
    #pragma unroll
    for (int ni = 0; ni < 4; ni++) {
        float f[2][4];
        float2 lo = __half22float2(*(const __half2*)&c_[0][ni][0]);
        float2 hi = __half22float2(*(const __half2*)&c_[0][ni][1]);
        f[0][0] = lo.x; f[0][1] = lo.y; f[0][2] = hi.x; f[0][3] = hi.y;
        lo = __half22float2(*(const __half2*)&c_[1][ni][0]);
        hi = __half22float2(*(const __half2*)&c_[1][ni][1]);
        f[1][0] = lo.x; f[1][1] = lo.y; f[1][2] = hi.x; f[1][3] = hi.y;
        #pragma unroll
        for (int mi = 0; mi < 2; mi++)
            #pragma unroll
            for (int h = 0; h < 2; h++) {
                const int bi = mi * 2 + h;
                const int row = rbase + mi * 16 + h * 8;
                #pragma unroll
                for (int bb = 0; bb < 2; bb++) {
                    float v = f[mi][h * 2 + bb];
                    int col = colb + ni * 8 + bb;
                    if (diag && col == row) continue;
                    if (v > best[bi]) { best[bi] = v; bidx[bi] = col; }
                }
            }
        if (!diag) {
            #pragma unroll
            for (int bb = 0; bb < 2; bb++) {
                float bv = f[0][bb];       int br = rbase;
                float v;
                v = f[0][2 + bb]; if (v > bv) { bv = v; br = rbase + 8;  }
                v = f[1][bb];     if (v > bv) { bv = v; br = rbase + 16; }
                v = f[1][2 + bb]; if (v > bv) { bv = v; br = rbase + 24; }
                unsigned long long p = pack_vi(bv, br);
                p = u64max(p, shfl_xor_u64(p, 4));
                p = u64max(p, shfl_xor_u64(p, 8));
                p = u64max(p, shfl_xor_u64(p, 16));
                if ((l >> 2) == 0)
                    atomicMax(&g_best[colb + ni * 8 + bb], p);
            }
        }
    }
}

__device__ __forceinline__ void flush_rows(int rowblk, int rloc, int l,
                                           float best[4], int bidx[4]) {
    #pragma unroll
    for (int bi = 0; bi < 4; bi++) {
        unsigned long long p = pack_vi(best[bi], bidx[bi]);
        p = u64max(p, shfl_xor_u64(p, 1));
        p = u64max(p, shfl_xor_u64(p, 2));
        if ((l & 3) == 0) {
            int row = rowblk * 128 + rloc + (bi >> 1) * 16 + (bi & 1) * 8;
            atomicMax(&g_best[row], p);
        }
        best[bi] = -2.0f; bidx[bi] = 0;
    }
}

__device__ __forceinline__ int free_slot(int sa, int sb) {
    if (sa != 0 && sb != 0) return 0;
    if (sa != 1 && sb != 1) return 1;
    return 2;
}

// ---------------------------------------------------------------------------
// Kernel 2: persistent balanced upper-tri GEMM-argmax. 148 CTAs, 512 thr,
// 16 warps (4x4 grid of 32x32 warp tiles); double-banked fp16 accumulators
// with the fold of tile n-1 interleaved inside tile n's k-loop.
__global__ void __launch_bounds__(NTHR, 1) koleo_gemm() {
    extern __shared__ __align__(16) char smem[];
    const uint32_t su = smem_u32(smem);
    const int tid = threadIdx.x;
    const int l   = tid & 31;
    const int wid = tid >> 5;
    const int wm  = wid >> 2;            // 0..3 (M)
    const int wn  = wid & 3;             // 0..3 (N)
    const int rloc = wm * 32 + (l >> 2);
    const int b   = blockIdx.x;

    const int cnt = 14 + (b < 8 ? 1 : 0);
    int s = b * 14 + (b < 8 ? b : 8);
    int i = 0;
    while (s >= 64 - i) { s -= 64 - i; i++; }
    int j = i + s;

    const uint32_t aoff = (uint32_t)((wm * 32 + (l & 15)) * RSB + (l >> 4) * 16);
    const uint32_t boff = (uint32_t)((wn * 32 + (l & 7) + ((l >> 4) << 3)) * RSB +
                                     ((l >> 3) & 1) * 16);

    // initial loads (full tiles)
    int sa = 0, sb;
    #pragma unroll
    for (int q = 0; q < 8; q++) {
        int flat = tid + q * NTHR;
        int r = flat >> 5;
        int c = flat & 31;
        CP16(su + r * RSB + c * 16, g_xh + (size_t)i * 128 * DIM + (size_t)r * DIM + c * 8);
    }
    if (j != i) {
        #pragma unroll
        for (int q = 0; q < 8; q++) {
            int flat = tid + q * NTHR;
            int r = flat >> 5;
            int c = flat & 31;
            CP16(su + ATILE + r * RSB + c * 16,
                 g_xh + (size_t)j * 128 * DIM + (size_t)r * DIM + c * 8);
        }
        sb = 1;
    } else sb = 0;
    CPCOMMIT();

    float best[4] = {-2.0f, -2.0f, -2.0f, -2.0f};
    int   bidx[4] = {0, 0, 0, 0};
    uint32_t c0[2][4][2], c1[2][4][2];
    int pi = 0, pj = 0;

    #pragma unroll 1
    for (int n = 0; n < cnt; n++) {
        CPWAIT0();
        __syncthreads();

        int nsa = sa, nsb = sb, ii2 = i, jj2 = j;
        bool pf = (n + 1 < cnt);
        uint32_t pfdst = 0;
        const __half* pfsrc = nullptr;
        if (pf) {
            int fs = free_slot(sa, sb);
            pfdst = su + fs * ATILE;
            if (j + 1 < 64) {
                pfsrc = g_xh + (size_t)(j + 1) * 128 * DIM;
                nsb = fs; jj2 = j + 1;
            } else {
                pfsrc = g_xh + (size_t)(i + 1) * 128 * DIM;
                nsa = fs; nsb = fs; ii2 = i + 1; jj2 = i + 1;
            }
        }

        const bool dofold = (n > 0);
        const int  prbase = pi * 128 + rloc;
        const int  pcolb  = pj * 128 + wn * 32 + (l & 3) * 2;
        const bool pdiag  = (pi == pj);

        if ((n & 1) == 0)
            mma_tile_fold(c0, c1, su + sa * ATILE, su + sb * ATILE, aoff, boff,
                          pf, pfdst, pfsrc, tid, dofold, prbase, pcolb, pdiag,
                          l, best, bidx);
        else
            mma_tile_fold(c1, c0, su + sa * ATILE, su + sb * ATILE, aoff, boff,
                          pf, pfdst, pfsrc, tid, dofold, prbase, pcolb, pdiag,
                          l, best, bidx);
        if (pf) CPCOMMIT();
        if (dofold && pi != i)
            flush_rows(pi, rloc, l, best, bidx);

        pi = i; pj = j;
        sa = nsa; sb = nsb; i = ii2; j = jj2;
    }

    // fold + flush the final tile
    {
        const int  prbase = pi * 128 + rloc;
        const int  pcolb  = pj * 128 + wn * 32 + (l & 3) * 2;
        const bool pdiag  = (pi == pj);
        if (((cnt - 1) & 1) == 0)
            fold_tile(c0, prbase, pcolb, pdiag, l, best, bidx);
        else
            fold_tile(c1, prbase, pcolb, pdiag, l, best, bidx);
        flush_rows(pi, rloc, l, best, bidx);
    }
}

// ---------------------------------------------------------------------------
// Kernel 3: per-row distance + log + fused reduction. One warp per row.
__global__ void koleo_dist(const float* __restrict__ x, float* __restrict__ out) {
    __shared__ float sh[8];
    int row  = blockIdx.x * 8 + (threadIdx.x >> 5);
    int lane = threadIdx.x & 31;
    int nb   = unpack_idx(g_best[row]);
    float ii = g_inv[row];
    float ij = g_inv[nb];
    const float4* xi = (const float4*)(x + (size_t)row * DIM);
    const float4* xj = (const float4*)(x + (size_t)nb  * DIM);
    float s = 0.0f;
    #pragma unroll
    for (int c = 0; c < 2; c++) {
        float4 a = xi[lane + c * 32];
        float4 b = xj[lane + c * 32];
        float d0 = a.x * ii - b.x * ij + kEPS, d1 = a.y * ii - b.y * ij + kEPS;
        float d2 = a.z * ii - b.z * ij + kEPS, d3 = a.w * ii - b.w * ij + kEPS;
        s = fmaf(d0, d0, s); s = fmaf(d1, d1, s);
        s = fmaf(d2, d2, s); s = fmaf(d3, d3, s);
    }
    #pragma unroll
    for (int o = 16; o > 0; o >>= 1) s += __shfl_xor_sync(0xffffffffu, s, o);
    if (lane == 0) sh[threadIdx.x >> 5] = logf(sqrtf(s) + kEPS);
    __syncthreads();
    if (threadIdx.x == 0) {
        float t = sh[0] + sh[1] + sh[2] + sh[3] + sh[4] + sh[5] + sh[6] + sh[7];
        atomicAdd(out, t * (-1.0f / (float)BROWS));
    }
}

// ---------------------------------------------------------------------------
extern "C" void kernel_launch(void* const* d_in, const int* in_sizes, int n_in,
                              void* d_out, int out_size) {
    const float* student = (const float*)d_in[0];
    float* out = (float*)d_out;
    (void)in_sizes; (void)n_in; (void)out_size;

    const int smem_bytes = 3 * ATILE;      // 202752 B dynamic
    cudaFuncSetAttribute(koleo_gemm, cudaFuncAttributeMaxDynamicSharedMemorySize, smem_bytes);

    koleo_normcvt<<<BROWS / 8, 256>>>(student, out);
    koleo_gemm<<<NCTA, NTHR, smem_bytes>>>();
    koleo_dist<<<BROWS / 8, 256>>>(student, out);
}

// round 15
// speedup vs baseline: 2.1836x; 1.0494x over previous
#include <cuda_runtime.h>
#include <cuda_fp16.h>
#include <math.h>
#include <stdint.h>

#define BROWS 8192
#define DIM   256
#define RSB   528           // smem row stride bytes (256 halves + 8 pad)
#define ATILE (128 * RSB)   // 67584 B per tile slot
#define NCTA  152           // GB300: 152 SMs
#define NTHR  512

static __device__ __constant__ float kEPS = 1e-8f;

// ------------------------- device scratch ----------------------------------
__device__ __align__(16) __half g_xh[BROWS * DIM];   // normalized fp16 (4 MB)
__device__ float                g_inv[BROWS];        // per-row 1/norm
__device__ unsigned long long   g_best[BROWS];

// ------------------------- helpers -----------------------------------------
__device__ __forceinline__ uint32_t smem_u32(const void* p) {
    uint32_t a;
    asm("{ .reg .u64 t; cvta.to.shared.u64 t, %1; cvt.u32.u64 %0, t; }" : "=r"(a) : "l"(p));
    return a;
}
__device__ __forceinline__ void ldsm4(uint32_t r[4], uint32_t a) {
    asm volatile("ldmatrix.sync.aligned.m8n8.x4.shared.b16 {%0,%1,%2,%3}, [%4];"
                 : "=r"(r[0]), "=r"(r[1]), "=r"(r[2]), "=r"(r[3]) : "r"(a));
}
__device__ __forceinline__ void mma16816h(uint32_t c[2], const uint32_t a[4],
                                          uint32_t b0, uint32_t b1) {
    asm volatile("mma.sync.aligned.m16n8k16.row.col.f16.f16.f16.f16 "
                 "{%0,%1}, {%2,%3,%4,%5}, {%6,%7}, {%0,%1};"
                 : "+r"(c[0]), "+r"(c[1])
                 : "r"(a[0]), "r"(a[1]), "r"(a[2]), "r"(a[3]), "r"(b0), "r"(b1));
}
#define CP16(dst, src)  asm volatile("cp.async.cg.shared.global [%0], [%1], 16;" :: "r"(dst), "l"(src) : "memory")
#define CPCOMMIT()      asm volatile("cp.async.commit_group;" ::: "memory")
#define CPWAIT0()       asm volatile("cp.async.wait_group 0;" ::: "memory")

// pack: high 32 = orderable key (dot+2 > 0), low 32 = 8191-idx (tie -> smaller idx)
__device__ __forceinline__ unsigned long long pack_vi(float v, int idx) {
    return ((unsigned long long)__float_as_uint(v + 2.0f) << 32) |
           (unsigned)(8191 - idx);
}
__device__ __forceinline__ int unpack_idx(unsigned long long p) {
    return 8191 - (int)(p & 0xFFFFFFFFull);
}
__device__ __forceinline__ unsigned long long u64max(unsigned long long a,
                                                     unsigned long long b) {
    return a > b ? a : b;
}
__device__ __forceinline__ unsigned long long shfl_xor_u64(unsigned long long v, int m) {
    uint32_t lo = (uint32_t)v, hi = (uint32_t)(v >> 32);
    lo = __shfl_xor_sync(0xffffffffu, lo, m);
    hi = __shfl_xor_sync(0xffffffffu, hi, m);
    return ((unsigned long long)hi << 32) | lo;
}

// ---------------------------------------------------------------------------
// Kernel 1: normalize -> fp16 + inv-norm. 1024 blocks x 128 thr; each warp
// handles 2 rows with all 4 float4 loads issued up front (MLP=4/thread).
__global__ void koleo_normcvt(const float* __restrict__ x, float* __restrict__ out) {
    int wid  = threadIdx.x >> 5;             // 0..3
    int lane = threadIdx.x & 31;
    int r0 = blockIdx.x * 8 + wid * 2;
    int r1 = r0 + 1;
    const float4* s0 = (const float4*)(x + (size_t)r0 * DIM);
    const float4* s1 = (const float4*)(x + (size_t)r1 * DIM);
    float4 a0 = s0[lane];
    float4 a1 = s0[lane + 32];
    float4 b0 = s1[lane];
    float4 b1 = s1[lane + 32];
    float sa = a0.x*a0.x + a0.y*a0.y + a0.z*a0.z + a0.w*a0.w
             + a1.x*a1.x + a1.y*a1.y + a1.z*a1.z + a1.w*a1.w;
    float sb = b0.x*b0.x + b0.y*b0.y + b0.z*b0.z + b0.w*b0.w
             + b1.x*b1.x + b1.y*b1.y + b1.z*b1.z + b1.w*b1.w;
    #pragma unroll
    for (int o = 16; o > 0; o >>= 1) {
        sa += __shfl_xor_sync(0xffffffffu, sa, o);
        sb += __shfl_xor_sync(0xffffffffu, sb, o);
    }
    float ia = 1.0f / fmaxf(sqrtf(sa), kEPS);
    float ib = 1.0f / fmaxf(sqrtf(sb), kEPS);

    ushort4 H;
    ushort4* d0 = (ushort4*)(g_xh + (size_t)r0 * DIM);
    ushort4* d1 = (ushort4*)(g_xh + (size_t)r1 * DIM);
    H.x = __half_as_ushort(__float2half_rn(a0.x * ia));
    H.y = __half_as_ushort(__float2half_rn(a0.y * ia));
    H.z = __half_as_ushort(__float2half_rn(a0.z * ia));
    H.w = __half_as_ushort(__float2half_rn(a0.w * ia));
    d0[lane] = H;
    H.x = __half_as_ushort(__float2half_rn(a1.x * ia));
    H.y = __half_as_ushort(__float2half_rn(a1.y * ia));
    H.z = __half_as_ushort(__float2half_rn(a1.z * ia));
    H.w = __half_as_ushort(__float2half_rn(a1.w * ia));
    d0[lane + 32] = H;
    H.x = __half_as_ushort(__float2half_rn(b0.x * ib));
    H.y = __half_as_ushort(__float2half_rn(b0.y * ib));
    H.z = __half_as_ushort(__float2half_rn(b0.z * ib));
    H.w = __half_as_ushort(__float2half_rn(b0.w * ib));
    d1[lane] = H;
    H.x = __half_as_ushort(__float2half_rn(b1.x * ib));
    H.y = __half_as_ushort(__float2half_rn(b1.y * ib));
    H.z = __half_as_ushort(__float2half_rn(b1.z * ib));
    H.w = __half_as_ushort(__float2half_rn(b1.w * ib));
    d1[lane + 32] = H;
    if (lane == 0) {
        g_inv[r0] = ia; g_best[r0] = 0ull;
        g_inv[r1] = ib; g_best[r1] = 0ull;
    }
    if (blockIdx.x == 0 && threadIdx.x == 0) out[0] = 0.0f;
}

// ---------------------------------------------------------------------------
// MMA of current tile into bank cc, fold of previous tile (bank cp) at
// k=12..15, next-tile cp.async prefetch at k=4..11.
__device__ __forceinline__ void mma_tile_fold(
    uint32_t (&cc)[2][4][2], const uint32_t (&cp)[2][4][2],
    uint32_t uA, uint32_t uB, uint32_t aoff, uint32_t boff,
    bool pf, uint32_t pfdst, const __half* __restrict__ pfsrc, int tid,
    bool dofold, int prbase, int pcolb, bool pdiag, int l,
    float best[4], int bidx[4]) {

    #pragma unroll
    for (int mi = 0; mi < 2; mi++)
        #pragma unroll
        for (int ni = 0; ni < 4; ni++) { cc[mi][ni][0] = 0u; cc[mi][ni][1] = 0u; }

    #pragma unroll
    for (int k = 0; k < 16; k++) {
        if (k >= 4 && k < 12 && pf) {
            int flat = tid + (k - 4) * NTHR;
            int r = flat >> 5;
            int c = flat & 31;
            CP16(pfdst + r * RSB + c * 16, pfsrc + (size_t)r * DIM + c * 8);
        }
        uint32_t a0[4], a1[4];
        ldsm4(a0, uA + aoff + k * 32);
        ldsm4(a1, uA + aoff + 16 * RSB + k * 32);
        uint32_t b[2][4];
        ldsm4(b[0], uB + boff + k * 32);
        ldsm4(b[1], uB + boff + 16 * RSB + k * 32);
        #pragma unroll
        for (int ni = 0; ni < 4; ni++) {
            uint32_t b0 = b[ni >> 1][(ni & 1) * 2];
            uint32_t b1 = b[ni >> 1][(ni & 1) * 2 + 1];
            mma16816h(cc[0][ni], a0, b0, b1);
            mma16816h(cc[1][ni], a1, b0, b1);
        }

        if (k >= 12 && dofold) {
            const int ni = k - 12;
            float f[2][4];
            {
                float2 lo = __half22float2(*(const __half2*)&cp[0][ni][0]);
                float2 hi = __half22float2(*(const __half2*)&cp[0][ni][1]);
                f[0][0] = lo.x; f[0][1] = lo.y; f[0][2] = hi.x; f[0][3] = hi.y;
                lo = __half22float2(*(const __half2*)&cp[1][ni][0]);
                hi = __half22float2(*(const __half2*)&cp[1][ni][1]);
                f[1][0] = lo.x; f[1][1] = lo.y; f[1][2] = hi.x; f[1][3] = hi.y;
            }
            if (pdiag) {
                #pragma unroll
                for (int mi = 0; mi < 2; mi++)
                    #pragma unroll
                    for (int h = 0; h < 2; h++) {
                        const int bi = mi * 2 + h;
                        const int row = prbase + mi * 16 + h * 8;
                        #pragma unroll
                        for (int bb = 0; bb < 2; bb++) {
                            float v = f[mi][h * 2 + bb];
                            int col = pcolb + ni * 8 + bb;
                            if (col != row && v > best[bi]) { best[bi] = v; bidx[bi] = col; }
                        }
                    }
            } else {
                #pragma unroll
                for (int mi = 0; mi < 2; mi++)
                    #pragma unroll
                    for (int h = 0; h < 2; h++) {
                        const int bi = mi * 2 + h;
                        #pragma unroll
                        for (int bb = 0; bb < 2; bb++) {
                            float v = f[mi][h * 2 + bb];
                            int col = pcolb + ni * 8 + bb;
                            if (v > best[bi]) { best[bi] = v; bidx[bi] = col; }
                        }
                    }
                #pragma unroll
                for (int bb = 0; bb < 2; bb++) {
                    float bv = f[0][bb];       int br = prbase;
                    float v;
                    v = f[0][2 + bb]; if (v > bv) { bv = v; br = prbase + 8;  }
                    v = f[1][bb];     if (v > bv) { bv = v; br = prbase + 16; }
                    v = f[1][2 + bb]; if (v > bv) { bv = v; br = prbase + 24; }
                    unsigned long long p = pack_vi(bv, br);
                    p = u64max(p, shfl_xor_u64(p, 4));
                    p = u64max(p, shfl_xor_u64(p, 8));
                    p = u64max(p, shfl_xor_u64(p, 16));
                    if ((l >> 2) == 0)
                        atomicMax(&g_best[pcolb + ni * 8 + bb], p);
                }
            }
        }
    }
}

// standalone fold (for the last tile)
__device__ __forceinline__ void fold_tile(const uint32_t (&c_)[2][4][2],
                                          int rbase, int colb, bool diag, int l,
                                          float best[4], int bidx[4]) {
    #pragma unroll
    for (int ni = 0; ni < 4; ni++) {
        float f[2][4];
        float2 lo = __half22float2(*(const __half2*)&c_[0][ni][0]);
        float2 hi = __half22float2(*(const __half2*)&c_[0][ni][1]);
        f[0][0] = lo.x; f[0][1] = lo.y; f[0][2] = hi.x; f[0][3] = hi.y;
        lo = __half22float2(*(const __half2*)&c_[1][ni][0]);
        hi = __half22float2(*(const __half2*)&c_[1][ni][1]);
        f[1][0] = lo.x; f[1][1] = lo.y; f[1][2] = hi.x; f[1][3] = hi.y;
        #pragma unroll
        for (int mi = 0; mi < 2; mi++)
            #pragma unroll
            for (int h = 0; h < 2; h++) {
                const int bi = mi * 2 + h;
                const int row = rbase + mi * 16 + h * 8;
                #pragma unroll
                for (int bb = 0; bb < 2; bb++) {
                    float v = f[mi][h * 2 + bb];
                    int col = colb + ni * 8 + bb;
                    if (diag && col == row) continue;
                    if (v > best[bi]) { best[bi] = v; bidx[bi] = col; }
                }
            }
        if (!diag) {
            #pragma unroll
            for (int bb = 0; bb < 2; bb++) {
                float bv = f[0][bb];       int br = rbase;
                float v;
                v = f[0][2 + bb]; if (v > bv) { bv = v; br = rbase + 8;  }
                v = f[1][bb];     if (v > bv) { bv = v; br = rbase + 16; }
                v = f[1][2 + bb]; if (v > bv) { bv = v; br = rbase + 24; }
                unsigned long long p = pack_vi(bv, br);
                p = u64max(p, shfl_xor_u64(p, 4));
                p = u64max(p, shfl_xor_u64(p, 8));
                p = u64max(p, shfl_xor_u64(p, 16));
                if ((l >> 2) == 0)
                    atomicMax(&g_best[colb + ni * 8 + bb], p);
            }
        }
    }
}

__device__ __forceinline__ void flush_rows(int rowblk, int rloc, int l,
                                           float best[4], int bidx[4]) {
    #pragma unroll
    for (int bi = 0; bi < 4; bi++) {
        unsigned long long p = pack_vi(best[bi], bidx[bi]);
        p = u64max(p, shfl_xor_u64(p, 1));
        p = u64max(p, shfl_xor_u64(p, 2));
        if ((l & 3) == 0) {
            int row = rowblk * 128 + rloc + (bi >> 1) * 16 + (bi & 1) * 8;
            atomicMax(&g_best[row], p);
        }
        best[bi] = -2.0f; bidx[bi] = 0;
    }
}

__device__ __forceinline__ int free_slot(int sa, int sb) {
    if (sa != 0 && sb != 0) return 0;
    if (sa != 1 && sb != 1) return 1;
    return 2;
}

// ---------------------------------------------------------------------------
// Kernel 2: persistent balanced upper-tri GEMM-argmax. 152 CTAs (GB300), 512
// thr, 16 warps (4x4 grid of 32x32 warp tiles); banked fp16 accumulators with
// previous-tile fold interleaved inside the k-loop.
__global__ void __launch_bounds__(NTHR, 1) koleo_gemm() {
    extern __shared__ __align__(16) char smem[];
    const uint32_t su = smem_u32(smem);
    const int tid = threadIdx.x;
    const int l   = tid & 31;
    const int wid = tid >> 5;
    const int wm  = wid >> 2;            // 0..3 (M)
    const int wn  = wid & 3;             // 0..3 (N)
    const int rloc = wm * 32 + (l >> 2);
    const int b   = blockIdx.x;

    // 2080 tiles = 152*13 + 104: first 104 CTAs take 14 tiles, rest 13.
    const int cnt = 13 + (b < 104 ? 1 : 0);
    int s = b * 13 + (b < 104 ? b : 104);
    int i = 0;
    while (s >= 64 - i) { s -= 64 - i; i++; }
    int j = i + s;

    const uint32_t aoff = (uint32_t)((wm * 32 + (l & 15)) * RSB + (l >> 4) * 16);
    const uint32_t boff = (uint32_t)((wn * 32 + (l & 7) + ((l >> 4) << 3)) * RSB +
                                     ((l >> 3) & 1) * 16);

    // initial loads (full tiles)
    int sa = 0, sb;
    #pragma unroll
    for (int q = 0; q < 8; q++) {
        int flat = tid + q * NTHR;
        int r = flat >> 5;
        int c = flat & 31;
        CP16(su + r * RSB + c * 16, g_xh + (size_t)i * 128 * DIM + (size_t)r * DIM + c * 8);
    }
    if (j != i) {
        #pragma unroll
        for (int q = 0; q < 8; q++) {
            int flat = tid + q * NTHR;
            int r = flat >> 5;
            int c = flat & 31;
            CP16(su + ATILE + r * RSB + c * 16,
                 g_xh + (size_t)j * 128 * DIM + (size_t)r * DIM + c * 8);
        }
        sb = 1;
    } else sb = 0;
    CPCOMMIT();

    float best[4] = {-2.0f, -2.0f, -2.0f, -2.0f};
    int   bidx[4] = {0, 0, 0, 0};
    uint32_t c0[2][4][2], c1[2][4][2];
    int pi = 0, pj = 0;

    #pragma unroll 1
    for (int n = 0; n < cnt; n++) {
        CPWAIT0();
        __syncthreads();

        int nsa = sa, nsb = sb, ii2 = i, jj2 = j;
        bool pf = (n + 1 < cnt);
        uint32_t pfdst = 0;
        const __half* pfsrc = nullptr;
        if (pf) {
            int fs = free_slot(sa, sb);
            pfdst = su + fs * ATILE;
            if (j + 1 < 64) {
                pfsrc = g_xh + (size_t)(j + 1) * 128 * DIM;
                nsb = fs; jj2 = j + 1;
            } else {
                pfsrc = g_xh + (size_t)(i + 1) * 128 * DIM;
                nsa = fs; nsb = fs; ii2 = i + 1; jj2 = i + 1;
            }
        }

        const bool dofold = (n > 0);
        const int  prbase = pi * 128 + rloc;
        const int  pcolb  = pj * 128 + wn * 32 + (l & 3) * 2;
        const bool pdiag  = (pi == pj);

        if ((n & 1) == 0)
            mma_tile_fold(c0, c1, su + sa * ATILE, su + sb * ATILE, aoff, boff,
                          pf, pfdst, pfsrc, tid, dofold, prbase, pcolb, pdiag,
                          l, best, bidx);
        else
            mma_tile_fold(c1, c0, su + sa * ATILE, su + sb * ATILE, aoff, boff,
                          pf, pfdst, pfsrc, tid, dofold, prbase, pcolb, pdiag,
                          l, best, bidx);
        if (pf) CPCOMMIT();
        if (dofold && pi != i)
            flush_rows(pi, rloc, l, best, bidx);

        pi = i; pj = j;
        sa = nsa; sb = nsb; i = ii2; j = jj2;
    }

    // fold + flush the final tile
    {
        const int  prbase = pi * 128 + rloc;
        const int  pcolb  = pj * 128 + wn * 32 + (l & 3) * 2;
        const bool pdiag  = (pi == pj);
        if (((cnt - 1) & 1) == 0)
            fold_tile(c0, prbase, pcolb, pdiag, l, best, bidx);
        else
            fold_tile(c1, prbase, pcolb, pdiag, l, best, bidx);
        flush_rows(pi, rloc, l, best, bidx);
    }
}

// ---------------------------------------------------------------------------
// Kernel 3: per-row distance + log + fused reduction. One warp per row;
// xi loads issued before the g_best -> g_inv -> xj dependent chain resolves.
__global__ void koleo_dist(const float* __restrict__ x, float* __restrict__ out) {
    __shared__ float sh[8];
    int row  = blockIdx.x * 8 + (threadIdx.x >> 5);
    int lane = threadIdx.x & 31;
    const float4* xi = (const float4*)(x + (size_t)row * DIM);
    float4 a0 = xi[lane];                 // independent of the chain
    float4 a1 = xi[lane + 32];
    unsigned long long pb = g_best[row];
    float ii = g_inv[row];
    int nb = unpack_idx(pb);
    float ij = g_inv[nb];
    const float4* xj = (const float4*)(x + (size_t)nb * DIM);
    float4 b0 = xj[lane];
    float4 b1 = xj[lane + 32];

    float s = 0.0f;
    float d;
    d = a0.x * ii - b0.x * ij + kEPS; s = fmaf(d, d, s);
    d = a0.y * ii - b0.y * ij + kEPS; s = fmaf(d, d, s);
    d = a0.z * ii - b0.z * ij + kEPS; s = fmaf(d, d, s);
    d = a0.w * ii - b0.w * ij + kEPS; s = fmaf(d, d, s);
    d = a1.x * ii - b1.x * ij + kEPS; s = fmaf(d, d, s);
    d = a1.y * ii - b1.y * ij + kEPS; s = fmaf(d, d, s);
    d = a1.z * ii - b1.z * ij + kEPS; s = fmaf(d, d, s);
    d = a1.w * ii - b1.w * ij + kEPS; s = fmaf(d, d, s);
    #pragma unroll
    for (int o = 16; o > 0; o >>= 1) s += __shfl_xor_sync(0xffffffffu, s, o);
    if (lane == 0) sh[threadIdx.x >> 5] = logf(sqrtf(s) + kEPS);
    __syncthreads();
    if (threadIdx.x == 0) {
        float t = sh[0] + sh[1] + sh[2] + sh[3] + sh[4] + sh[5] + sh[6] + sh[7];
        atomicAdd(out, t * (-1.0f / (float)BROWS));
    }
}

// ---------------------------------------------------------------------------
extern "C" void kernel_launch(void* const* d_in, const int* in_sizes, int n_in,
                              void* d_out, int out_size) {
    const float* student = (const float*)d_in[0];
    float* out = (float*)d_out;
    (void)in_sizes; (void)n_in; (void)out_size;

    const int smem_bytes = 3 * ATILE;      // 202752 B dynamic
    cudaFuncSetAttribute(koleo_gemm, cudaFuncAttributeMaxDynamicSharedMemorySize, smem_bytes);

    koleo_normcvt<<<BROWS / 8, 128>>>(student, out);
    koleo_gemm<<<NCTA, NTHR, smem_bytes>>>();
    koleo_dist<<<BROWS / 8, 256>>>(student, out);
}

// round 16
// speedup vs baseline: 2.2031x; 1.0089x over previous
#include <cuda_runtime.h>
#include <cuda_fp16.h>
#include <math.h>
#include <stdint.h>

#define BROWS 8192
#define DIM   256
#define RSB   528           // smem row stride bytes (256 halves + 8 pad)
#define ATILE (128 * RSB)   // 67584 B per tile slot
#define NCTA  152           // GB300: 152 SMs
#define NTHR  512

static __device__ __constant__ float kEPS = 1e-8f;

// ------------------------- device scratch ----------------------------------
__device__ __align__(16) __half g_xh[BROWS * DIM];   // normalized fp16 (4 MB)
__device__ float                g_inv[BROWS];        // per-row 1/norm
__device__ unsigned long long   g_best[BROWS];

// ------------------------- helpers -----------------------------------------
__device__ __forceinline__ uint32_t smem_u32(const void* p) {
    uint32_t a;
    asm("{ .reg .u64 t; cvta.to.shared.u64 t, %1; cvt.u32.u64 %0, t; }" : "=r"(a) : "l"(p));
    return a;
}
__device__ __forceinline__ void ldsm4(uint32_t r[4], uint32_t a) {
    asm volatile("ldmatrix.sync.aligned.m8n8.x4.shared.b16 {%0,%1,%2,%3}, [%4];"
                 : "=r"(r[0]), "=r"(r[1]), "=r"(r[2]), "=r"(r[3]) : "r"(a));
}
__device__ __forceinline__ void mma16816h(uint32_t c[2], const uint32_t a[4],
                                          uint32_t b0, uint32_t b1) {
    asm volatile("mma.sync.aligned.m16n8k16.row.col.f16.f16.f16.f16 "
                 "{%0,%1}, {%2,%3,%4,%5}, {%6,%7}, {%0,%1};"
                 : "+r"(c[0]), "+r"(c[1])
                 : "r"(a[0]), "r"(a[1]), "r"(a[2]), "r"(a[3]), "r"(b0), "r"(b1));
}
#define CP16(dst, src)  asm volatile("cp.async.cg.shared.global [%0], [%1], 16;" :: "r"(dst), "l"(src) : "memory")
#define CPCOMMIT()      asm volatile("cp.async.commit_group;" ::: "memory")
#define CPWAIT0()       asm volatile("cp.async.wait_group 0;" ::: "memory")

// pack: high 32 = orderable key (dot+2 > 0), low 32 = 8191-idx (tie -> smaller idx)
__device__ __forceinline__ unsigned long long pack_vi(float v, int idx) {
    return ((unsigned long long)__float_as_uint(v + 2.0f) << 32) |
           (unsigned)(8191 - idx);
}
__device__ __forceinline__ int unpack_idx(unsigned long long p) {
    return 8191 - (int)(p & 0xFFFFFFFFull);
}
__device__ __forceinline__ unsigned long long u64max(unsigned long long a,
                                                     unsigned long long b) {
    return a > b ? a : b;
}
__device__ __forceinline__ unsigned long long shfl_xor_u64(unsigned long long v, int m) {
    uint32_t lo = (uint32_t)v, hi = (uint32_t)(v >> 32);
    lo = __shfl_xor_sync(0xffffffffu, lo, m);
    hi = __shfl_xor_sync(0xffffffffu, hi, m);
    return ((unsigned long long)hi << 32) | lo;
}

// ---------------------------------------------------------------------------
// Kernel 1: normalize -> fp16 + inv-norm; zero g_best; zero out. 1 warp/row,
// 256 threads, 1024 blocks (empirically fastest config: 5.76us, occ ~73%).
__global__ void koleo_normcvt(const float* __restrict__ x, float* __restrict__ out) {
    int row  = blockIdx.x * 8 + (threadIdx.x >> 5);
    int lane = threadIdx.x & 31;
    const float4* src = (const float4*)(x + (size_t)row * DIM);
    float4 v0 = src[lane];
    float4 v1 = src[lane + 32];
    float s = v0.x*v0.x + v0.y*v0.y + v0.z*v0.z + v0.w*v0.w
            + v1.x*v1.x + v1.y*v1.y + v1.z*v1.z + v1.w*v1.w;
    #pragma unroll
    for (int o = 16; o > 0; o >>= 1) s += __shfl_xor_sync(0xffffffffu, s, o);
    float inv = 1.0f / fmaxf(sqrtf(s), kEPS);
    v0.x *= inv; v0.y *= inv; v0.z *= inv; v0.w *= inv;
    v1.x *= inv; v1.y *= inv; v1.z *= inv; v1.w *= inv;

    ushort4 H0, H1;
    H0.x = __half_as_ushort(__float2half_rn(v0.x));
    H0.y = __half_as_ushort(__float2half_rn(v0.y));
    H0.z = __half_as_ushort(__float2half_rn(v0.z));
    H0.w = __half_as_ushort(__float2half_rn(v0.w));
    H1.x = __half_as_ushort(__float2half_rn(v1.x));
    H1.y = __half_as_ushort(__float2half_rn(v1.y));
    H1.z = __half_as_ushort(__float2half_rn(v1.z));
    H1.w = __half_as_ushort(__float2half_rn(v1.w));
    ushort4* hdst = (ushort4*)(g_xh + (size_t)row * DIM);
    hdst[lane] = H0; hdst[lane + 32] = H1;
    if (lane == 0) { g_inv[row] = inv; g_best[row] = 0ull; }
    if (blockIdx.x == 0 && threadIdx.x == 0) out[0] = 0.0f;
}

// ---------------------------------------------------------------------------
// MMA of current tile into bank cc, fold of previous tile (bank cp) at
// k=12..15, next-tile cp.async prefetch at k=4..11.
__device__ __forceinline__ void mma_tile_fold(
    uint32_t (&cc)[2][4][2], const uint32_t (&cp)[2][4][2],
    uint32_t uA, uint32_t uB, uint32_t aoff, uint32_t boff,
    bool pf, uint32_t pfdst, const __half* __restrict__ pfsrc, int tid,
    bool dofold, int prbase, int pcolb, bool pdiag, int l,
    float best[4], int bidx[4]) {

    #pragma unroll
    for (int mi = 0; mi < 2; mi++)
        #pragma unroll
        for (int ni = 0; ni < 4; ni++) { cc[mi][ni][0] = 0u; cc[mi][ni][1] = 0u; }

    #pragma unroll
    for (int k = 0; k < 16; k++) {
        if (k >= 4 && k < 12 && pf) {
            int flat = tid + (k - 4) * NTHR;
            int r = flat >> 5;
            int c = flat & 31;
            CP16(pfdst + r * RSB + c * 16, pfsrc + (size_t)r * DIM + c * 8);
        }
        uint32_t a0[4], a1[4];
        ldsm4(a0, uA + aoff + k * 32);
        ldsm4(a1, uA + aoff + 16 * RSB + k * 32);
        uint32_t b[2][4];
        ldsm4(b[0], uB + boff + k * 32);
        ldsm4(b[1], uB + boff + 16 * RSB + k * 32);
        #pragma unroll
        for (int ni = 0; ni < 4; ni++) {
            uint32_t b0 = b[ni >> 1][(ni & 1) * 2];
            uint32_t b1 = b[ni >> 1][(ni & 1) * 2 + 1];
            mma16816h(cc[0][ni], a0, b0, b1);
            mma16816h(cc[1][ni], a1, b0, b1);
        }

        if (k >= 12 && dofold) {
            const int ni = k - 12;
            float f[2][4];
            {
                float2 lo = __half22float2(*(const __half2*)&cp[0][ni][0]);
                float2 hi = __half22float2(*(const __half2*)&cp[0][ni][1]);
                f[0][0] = lo.x; f[0][1] = lo.y; f[0][2] = hi.x; f[0][3] = hi.y;
                lo = __half22float2(*(const __half2*)&cp[1][ni][0]);
                hi = __half22float2(*(const __half2*)&cp[1][ni][1]);
                f[1][0] = lo.x; f[1][1] = lo.y; f[1][2] = hi.x; f[1][3] = hi.y;
            }
            if (pdiag) {
                #pragma unroll
                for (int mi = 0; mi < 2; mi++)
                    #pragma unroll
                    for (int h = 0; h < 2; h++) {
                        const int bi = mi * 2 + h;
                        const int row = prbase + mi * 16 + h * 8;
                        #pragma unroll
                        for (int bb = 0; bb < 2; bb++) {
                            float v = f[mi][h * 2 + bb];
                            int col = pcolb + ni * 8 + bb;
                            if (col != row && v > best[bi]) { best[bi] = v; bidx[bi] = col; }
                        }
                    }
            } else {
                #pragma unroll
                for (int mi = 0; mi < 2; mi++)
                    #pragma unroll
                    for (int h = 0; h < 2; h++) {
                        const int bi = mi * 2 + h;
                        #pragma unroll
                        for (int bb = 0; bb < 2; bb++) {
                            float v = f[mi][h * 2 + bb];
                            int col = pcolb + ni * 8 + bb;
                            if (v > best[bi]) { best[bi] = v; bidx[bi] = col; }
                        }
                    }
                #pragma unroll
                for (int bb = 0; bb < 2; bb++) {
                    float bv = f[0][bb];       int br = prbase;
                    float v;
                    v = f[0][2 + bb]; if (v > bv) { bv = v; br = prbase + 8;  }
                    v = f[1][bb];     if (v > bv) { bv = v; br = prbase + 16; }
                    v = f[1][2 + bb]; if (v > bv) { bv = v; br = prbase + 24; }
                    unsigned long long p = pack_vi(bv, br);
                    p = u64max(p, shfl_xor_u64(p, 4));
                    p = u64max(p, shfl_xor_u64(p, 8));
                    p = u64max(p, shfl_xor_u64(p, 16));
                    if ((l >> 2) == 0)
                        atomicMax(&g_best[pcolb + ni * 8 + bb], p);
                }
            }
        }
    }
}

// standalone fold (for the last tile)
__device__ __forceinline__ void fold_tile(const uint32_t (&c_)[2][4][2],
                                          int rbase, int colb, bool diag, int l,
                                          float best[4], int bidx[4]) {
    #pragma unroll
    for (int ni = 0; ni < 4; ni++) {
        float f[2][4];
        float2 lo = __half22float2(*(const __half2*)&c_[0][ni][0]);
        float2 hi = __half22float2(*(const __half2*)&c_[0][ni][1]);
        f[0][0] = lo.x; f[0][1] = lo.y; f[0][2] = hi.x; f[0][3] = hi.y;
        lo = __half22float2(*(const __half2*)&c_[1][ni][0]);
        hi = __half22float2(*(const __half2*)&c_[1][ni][1]);
        f[1][0] = lo.x; f[1][1] = lo.y; f[1][2] = hi.x; f[1][3] = hi.y;
        #pragma unroll
        for (int mi = 0; mi < 2; mi++)
            #pragma unroll
            for (int h = 0; h < 2; h++) {
                const int bi = mi * 2 + h;
                const int row = rbase + mi * 16 + h * 8;
                #pragma unroll
                for (int bb = 0; bb < 2; bb++) {
                    float v = f[mi][h * 2 + bb];
                    int col = colb + ni * 8 + bb;
                    if (diag && col == row) continue;
                    if (v > best[bi]) { best[bi] = v; bidx[bi] = col; }
                }
            }
        if (!diag) {
            #pragma unroll
            for (int bb = 0; bb < 2; bb++) {
                float bv = f[0][bb];       int br = rbase;
                float v;
                v = f[0][2 + bb]; if (v > bv) { bv = v; br = rbase + 8;  }
                v = f[1][bb];     if (v > bv) { bv = v; br = rbase + 16; }
                v = f[1][2 + bb]; if (v > bv) { bv = v; br = rbase + 24; }
                unsigned long long p = pack_vi(bv, br);
                p = u64max(p, shfl_xor_u64(p, 4));
                p = u64max(p, shfl_xor_u64(p, 8));
                p = u64max(p, shfl_xor_u64(p, 16));
                if ((l >> 2) == 0)
                    atomicMax(&g_best[colb + ni * 8 + bb], p);
            }
        }
    }
}

__device__ __forceinline__ void flush_rows(int rowblk, int rloc, int l,
                                           float best[4], int bidx[4]) {
    #pragma unroll
    for (int bi = 0; bi < 4; bi++) {
        unsigned long long p = pack_vi(best[bi], bidx[bi]);
        p = u64max(p, shfl_xor_u64(p, 1));
        p = u64max(p, shfl_xor_u64(p, 2));
        if ((l & 3) == 0) {
            int row = rowblk * 128 + rloc + (bi >> 1) * 16 + (bi & 1) * 8;
            atomicMax(&g_best[row], p);
        }
        best[bi] = -2.0f; bidx[bi] = 0;
    }
}

__device__ __forceinline__ int free_slot(int sa, int sb) {
    if (sa != 0 && sb != 0) return 0;
    if (sa != 1 && sb != 1) return 1;
    return 2;
}

// ---------------------------------------------------------------------------
// Kernel 2: persistent balanced upper-tri GEMM-argmax. 152 CTAs, 512 thr,
// 16 warps (4x4 grid of 32x32 warp tiles); banked fp16 accumulators with
// previous-tile fold interleaved inside the k-loop.
__global__ void __launch_bounds__(NTHR, 1) koleo_gemm() {
    extern __shared__ __align__(16) char smem[];
    const uint32_t su = smem_u32(smem);
    const int tid = threadIdx.x;
    const int l   = tid & 31;
    const int wid = tid >> 5;
    const int wm  = wid >> 2;            // 0..3 (M)
    const int wn  = wid & 3;             // 0..3 (N)
    const int rloc = wm * 32 + (l >> 2);
    const int b   = blockIdx.x;

    // 2080 tiles = 152*13 + 104: first 104 CTAs take 14 tiles, rest 13.
    const int cnt = 13 + (b < 104 ? 1 : 0);
    int s = b * 13 + (b < 104 ? b : 104);
    int i = 0;
    while (s >= 64 - i) { s -= 64 - i; i++; }
    int j = i + s;

    const uint32_t aoff = (uint32_t)((wm * 32 + (l & 15)) * RSB + (l >> 4) * 16);
    const uint32_t boff = (uint32_t)((wn * 32 + (l & 7) + ((l >> 4) << 3)) * RSB +
                                     ((l >> 3) & 1) * 16);

    // initial loads (full tiles)
    int sa = 0, sb;
    #pragma unroll
    for (int q = 0; q < 8; q++) {
        int flat = tid + q * NTHR;
        int r = flat >> 5;
        int c = flat & 31;
        CP16(su + r * RSB + c * 16, g_xh + (size_t)i * 128 * DIM + (size_t)r * DIM + c * 8);
    }
    if (j != i) {
        #pragma unroll
        for (int q = 0; q < 8; q++) {
            int flat = tid + q * NTHR;
            int r = flat >> 5;
            int c = flat & 31;
            CP16(su + ATILE + r * RSB + c * 16,
                 g_xh + (size_t)j * 128 * DIM + (size_t)r * DIM + c * 8);
        }
        sb = 1;
    } else sb = 0;
    CPCOMMIT();

    float best[4] = {-2.0f, -2.0f, -2.0f, -2.0f};
    int   bidx[4] = {0, 0, 0, 0};
    uint32_t c0[2][4][2], c1[2][4][2];
    int pi = 0, pj = 0;

    #pragma unroll 1
    for (int n = 0; n < cnt; n++) {
        CPWAIT0();
        __syncthreads();

        int nsa = sa, nsb = sb, ii2 = i, jj2 = j;
        bool pf = (n + 1 < cnt);
        uint32_t pfdst = 0;
        const __half* pfsrc = nullptr;
        if (pf) {
            int fs = free_slot(sa, sb);
            pfdst = su + fs * ATILE;
            if (j + 1 < 64) {
                pfsrc = g_xh + (size_t)(j + 1) * 128 * DIM;
                nsb = fs; jj2 = j + 1;
            } else {
                pfsrc = g_xh + (size_t)(i + 1) * 128 * DIM;
                nsa = fs; nsb = fs; ii2 = i + 1; jj2 = i + 1;
            }
        }

        const bool dofold = (n > 0);
        const int  prbase = pi * 128 + rloc;
        const int  pcolb  = pj * 128 + wn * 32 + (l & 3) * 2;
        const bool pdiag  = (pi == pj);

        if ((n & 1) == 0)
            mma_tile_fold(c0, c1, su + sa * ATILE, su + sb * ATILE, aoff, boff,
                          pf, pfdst, pfsrc, tid, dofold, prbase, pcolb, pdiag,
                          l, best, bidx);
        else
            mma_tile_fold(c1, c0, su + sa * ATILE, su + sb * ATILE, aoff, boff,
                          pf, pfdst, pfsrc, tid, dofold, prbase, pcolb, pdiag,
                          l, best, bidx);
        if (pf) CPCOMMIT();
        if (dofold && pi != i)
            flush_rows(pi, rloc, l, best, bidx);

        pi = i; pj = j;
        sa = nsa; sb = nsb; i = ii2; j = jj2;
    }

    // fold + flush the final tile
    {
        const int  prbase = pi * 128 + rloc;
        const int  pcolb  = pj * 128 + wn * 32 + (l & 3) * 2;
        const bool pdiag  = (pi == pj);
        if (((cnt - 1) & 1) == 0)
            fold_tile(c0, prbase, pcolb, pdiag, l, best, bidx);
        else
            fold_tile(c1, prbase, pcolb, pdiag, l, best, bidx);
        flush_rows(pi, rloc, l, best, bidx);
    }
}

// ---------------------------------------------------------------------------
// Kernel 3: per-row distance + log + fused reduction. One warp per row;
// xi loads issued before the g_best -> g_inv -> xj dependent chain resolves.
__global__ void koleo_dist(const float* __restrict__ x, float* __restrict__ out) {
    __shared__ float sh[8];
    int row  = blockIdx.x * 8 + (threadIdx.x >> 5);
    int lane = threadIdx.x & 31;
    const float4* xi = (const float4*)(x + (size_t)row * DIM);
    float4 a0 = xi[lane];
    float4 a1 = xi[lane + 32];
    unsigned long long pb = g_best[row];
    float ii = g_inv[row];
    int nb = unpack_idx(pb);
    float ij = g_inv[nb];
    const float4* xj = (const float4*)(x + (size_t)nb * DIM);
    float4 b0 = xj[lane];
    float4 b1 = xj[lane + 32];

    float s = 0.0f;
    float d;
    d = a0.x * ii - b0.x * ij + kEPS; s = fmaf(d, d, s);
    d = a0.y * ii - b0.y * ij + kEPS; s = fmaf(d, d, s);
    d = a0.z * ii - b0.z * ij + kEPS; s = fmaf(d, d, s);
    d = a0.w * ii - b0.w * ij + kEPS; s = fmaf(d, d, s);
    d = a1.x * ii - b1.x * ij + kEPS; s = fmaf(d, d, s);
    d = a1.y * ii - b1.y * ij + kEPS; s = fmaf(d, d, s);
    d = a1.z * ii - b1.z * ij + kEPS; s = fmaf(d, d, s);
    d = a1.w * ii - b1.w * ij + kEPS; s = fmaf(d, d, s);
    #pragma unroll
    for (int o = 16; o > 0; o >>= 1) s += __shfl_xor_sync(0xffffffffu, s, o);
    if (lane == 0) sh[threadIdx.x >> 5] = logf(sqrtf(s) + kEPS);
    __syncthreads();
    if (threadIdx.x == 0) {
        float t = sh[0] + sh[1] + sh[2] + sh[3] + sh[4] + sh[5] + sh[6] + sh[7];
        atomicAdd(out, t * (-1.0f / (float)BROWS));
    }
}

// ---------------------------------------------------------------------------
extern "C" void kernel_launch(void* const* d_in, const int* in_sizes, int n_in,
                              void* d_out, int out_size) {
    const float* student = (const float*)d_in[0];
    float* out = (float*)d_out;
    (void)in_sizes; (void)n_in; (void)out_size;

    const int smem_bytes = 3 * ATILE;      // 202752 B dynamic
    cudaFuncSetAttribute(koleo_gemm, cudaFuncAttributeMaxDynamicSharedMemorySize, smem_bytes);

    koleo_normcvt<<<BROWS / 8, 256>>>(student, out);
    koleo_gemm<<<NCTA, NTHR, smem_bytes>>>();
    koleo_dist<<<BROWS / 8, 256>>>(student, out);
}

// round 17
// speedup vs baseline: 2.2703x; 1.0305x over previous
#include <cuda_runtime.h>
#include <cuda_fp16.h>
#include <math.h>
#include <stdint.h>

#define BROWS 8192
#define DIM   256
#define RSB   528           // smem row stride bytes (256 halves + 8 pad)
#define ATILE (128 * RSB)   // 67584 B per tile slot
#define NCTA  152           // GB300: 152 SMs
#define NTHR  512

static __device__ __constant__ float kEPS = 1e-8f;

// ------------------------- device scratch ----------------------------------
__device__ __align__(16) __half g_xh[BROWS * DIM];   // normalized fp16 (4 MB)
__device__ unsigned long long   g_best[BROWS];

// ------------------------- helpers -----------------------------------------
__device__ __forceinline__ uint32_t smem_u32(const void* p) {
    uint32_t a;
    asm("{ .reg .u64 t; cvta.to.shared.u64 t, %1; cvt.u32.u64 %0, t; }" : "=r"(a) : "l"(p));
    return a;
}
__device__ __forceinline__ void ldsm4(uint32_t r[4], uint32_t a) {
    asm volatile("ldmatrix.sync.aligned.m8n8.x4.shared.b16 {%0,%1,%2,%3}, [%4];"
                 : "=r"(r[0]), "=r"(r[1]), "=r"(r[2]), "=r"(r[3]) : "r"(a));
}
__device__ __forceinline__ void mma16816h(uint32_t c[2], const uint32_t a[4],
                                          uint32_t b0, uint32_t b1) {
    asm volatile("mma.sync.aligned.m16n8k16.row.col.f16.f16.f16.f16 "
                 "{%0,%1}, {%2,%3,%4,%5}, {%6,%7}, {%0,%1};"
                 : "+r"(c[0]), "+r"(c[1])
                 : "r"(a[0]), "r"(a[1]), "r"(a[2]), "r"(a[3]), "r"(b0), "r"(b1));
}
#define CP16(dst, src)  asm volatile("cp.async.cg.shared.global [%0], [%1], 16;" :: "r"(dst), "l"(src) : "memory")
#define CPCOMMIT()      asm volatile("cp.async.commit_group;" ::: "memory")
#define CPWAIT0()       asm volatile("cp.async.wait_group 0;" ::: "memory")

// pack: high 32 = fp32 bits of (dot+2) (monotone, >0), low 32 = 8191-idx
__device__ __forceinline__ unsigned long long pack_vi(float v, int idx) {
    return ((unsigned long long)__float_as_uint(v + 2.0f) << 32) |
           (unsigned)(8191 - idx);
}
__device__ __forceinline__ unsigned long long u64max(unsigned long long a,
                                                     unsigned long long b) {
    return a > b ? a : b;
}
__device__ __forceinline__ unsigned long long shfl_xor_u64(unsigned long long v, int m) {
    uint32_t lo = (uint32_t)v, hi = (uint32_t)(v >> 32);
    lo = __shfl_xor_sync(0xffffffffu, lo, m);
    hi = __shfl_xor_sync(0xffffffffu, hi, m);
    return ((unsigned long long)hi << 32) | lo;
}

// ---------------------------------------------------------------------------
// Kernel 1: normalize -> fp16; zero g_best; zero out. 1 warp/row, 256 thr.
__global__ void koleo_normcvt(const float* __restrict__ x, float* __restrict__ out) {
    int row  = blockIdx.x * 8 + (threadIdx.x >> 5);
    int lane = threadIdx.x & 31;
    const float4* src = (const float4*)(x + (size_t)row * DIM);
    float4 v0 = src[lane];
    float4 v1 = src[lane + 32];
    float s = v0.x*v0.x + v0.y*v0.y + v0.z*v0.z + v0.w*v0.w
            + v1.x*v1.x + v1.y*v1.y + v1.z*v1.z + v1.w*v1.w;
    #pragma unroll
    for (int o = 16; o > 0; o >>= 1) s += __shfl_xor_sync(0xffffffffu, s, o);
    float inv = 1.0f / fmaxf(sqrtf(s), kEPS);
    v0.x *= inv; v0.y *= inv; v0.z *= inv; v0.w *= inv;
    v1.x *= inv; v1.y *= inv; v1.z *= inv; v1.w *= inv;

    ushort4 H0, H1;
    H0.x = __half_as_ushort(__float2half_rn(v0.x));
    H0.y = __half_as_ushort(__float2half_rn(v0.y));
    H0.z = __half_as_ushort(__float2half_rn(v0.z));
    H0.w = __half_as_ushort(__float2half_rn(v0.w));
    H1.x = __half_as_ushort(__float2half_rn(v1.x));
    H1.y = __half_as_ushort(__float2half_rn(v1.y));
    H1.z = __half_as_ushort(__float2half_rn(v1.z));
    H1.w = __half_as_ushort(__float2half_rn(v1.w));
    ushort4* hdst = (ushort4*)(g_xh + (size_t)row * DIM);
    hdst[lane] = H0; hdst[lane + 32] = H1;
    if (lane == 0) g_best[row] = 0ull;
    if (blockIdx.x == 0 && threadIdx.x == 0) out[0] = 0.0f;
}

// ---------------------------------------------------------------------------
// MMA of current tile into bank cc, fold of previous tile (bank cp) at
// k=12..15, next-tile cp.async prefetch at k=4..11.
__device__ __forceinline__ void mma_tile_fold(
    uint32_t (&cc)[2][4][2], const uint32_t (&cp)[2][4][2],
    uint32_t uA, uint32_t uB, uint32_t aoff, uint32_t boff,
    bool pf, uint32_t pfdst, const __half* __restrict__ pfsrc, int tid,
    bool dofold, int prbase, int pcolb, bool pdiag, int l,
    float best[4], int bidx[4]) {

    #pragma unroll
    for (int mi = 0; mi < 2; mi++)
        #pragma unroll
        for (int ni = 0; ni < 4; ni++) { cc[mi][ni][0] = 0u; cc[mi][ni][1] = 0u; }

    #pragma unroll
    for (int k = 0; k < 16; k++) {
        if (k >= 4 && k < 12 && pf) {
            int flat = tid + (k - 4) * NTHR;
            int r = flat >> 5;
            int c = flat & 31;
            CP16(pfdst + r * RSB + c * 16, pfsrc + (size_t)r * DIM + c * 8);
        }
        uint32_t a0[4], a1[4];
        ldsm4(a0, uA + aoff + k * 32);
        ldsm4(a1, uA + aoff + 16 * RSB + k * 32);
        uint32_t b[2][4];
        ldsm4(b[0], uB + boff + k * 32);
        ldsm4(b[1], uB + boff + 16 * RSB + k * 32);
        #pragma unroll
        for (int ni = 0; ni < 4; ni++) {
            uint32_t b0 = b[ni >> 1][(ni & 1) * 2];
            uint32_t b1 = b[ni >> 1][(ni & 1) * 2 + 1];
            mma16816h(cc[0][ni], a0, b0, b1);
            mma16816h(cc[1][ni], a1, b0, b1);
        }

        if (k >= 12 && dofold) {
            const int ni = k - 12;
            float f[2][4];
            {
                float2 lo = __half22float2(*(const __half2*)&cp[0][ni][0]);
                float2 hi = __half22float2(*(const __half2*)&cp[0][ni][1]);
                f[0][0] = lo.x; f[0][1] = lo.y; f[0][2] = hi.x; f[0][3] = hi.y;
                lo = __half22float2(*(const __half2*)&cp[1][ni][0]);
                hi = __half22float2(*(const __half2*)&cp[1][ni][1]);
                f[1][0] = lo.x; f[1][1] = lo.y; f[1][2] = hi.x; f[1][3] = hi.y;
            }
            if (pdiag) {
                #pragma unroll
                for (int mi = 0; mi < 2; mi++)
                    #pragma unroll
                    for (int h = 0; h < 2; h++) {
                        const int bi = mi * 2 + h;
                        const int row = prbase + mi * 16 + h * 8;
                        #pragma unroll
                        for (int bb = 0; bb < 2; bb++) {
                            float v = f[mi][h * 2 + bb];
                            int col = pcolb + ni * 8 + bb;
                            if (col != row && v > best[bi]) { best[bi] = v; bidx[bi] = col; }
                        }
                    }
            } else {
                #pragma unroll
                for (int mi = 0; mi < 2; mi++)
                    #pragma unroll
                    for (int h = 0; h < 2; h++) {
                        const int bi = mi * 2 + h;
                        #pragma unroll
                        for (int bb = 0; bb < 2; bb++) {
                            float v = f[mi][h * 2 + bb];
                            int col = pcolb + ni * 8 + bb;
                            if (v > best[bi]) { best[bi] = v; bidx[bi] = col; }
                        }
                    }
                #pragma unroll
                for (int bb = 0; bb < 2; bb++) {
                    float bv = f[0][bb];       int br = prbase;
                    float v;
                    v = f[0][2 + bb]; if (v > bv) { bv = v; br = prbase + 8;  }
                    v = f[1][bb];     if (v > bv) { bv = v; br = prbase + 16; }
                    v = f[1][2 + bb]; if (v > bv) { bv = v; br = prbase + 24; }
                    unsigned long long p = pack_vi(bv, br);
                    p = u64max(p, shfl_xor_u64(p, 4));
                    p = u64max(p, shfl_xor_u64(p, 8));
                    p = u64max(p, shfl_xor_u64(p, 16));
                    if ((l >> 2) == 0)
                        atomicMax(&g_best[pcolb + ni * 8 + bb], p);
                }
            }
        }
    }
}

// standalone fold (for the last tile)
__device__ __forceinline__ void fold_tile(const uint32_t (&c_)[2][4][2],
                                          int rbase, int colb, bool diag, int l,
                                          float best[4], int bidx[4]) {
    #pragma unroll
    for (int ni = 0; ni < 4; ni++) {
        float f[2][4];
        float2 lo = __half22float2(*(const __half2*)&c_[0][ni][0]);
        float2 hi = __half22float2(*(const __half2*)&c_[0][ni][1]);
        f[0][0] = lo.x; f[0][1] = lo.y; f[0][2] = hi.x; f[0][3] = hi.y;
        lo = __half22float2(*(const __half2*)&c_[1][ni][0]);
        hi = __half22float2(*(const __half2*)&c_[1][ni][1]);
        f[1][0] = lo.x; f[1][1] = lo.y; f[1][2] = hi.x; f[1][3] = hi.y;
        #pragma unroll
        for (int mi = 0; mi < 2; mi++)
            #pragma unroll
            for (int h = 0; h < 2; h++) {
                const int bi = mi * 2 + h;
                const int row = rbase + mi * 16 + h * 8;
                #pragma unroll
                for (int bb = 0; bb < 2; bb++) {
                    float v = f[mi][h * 2 + bb];
                    int col = colb + ni * 8 + bb;
                    if (diag && col == row) continue;
                    if (v > best[bi]) { best[bi] = v; bidx[bi] = col; }
                }
            }
        if (!diag) {
            #pragma unroll
            for (int bb = 0; bb < 2; bb++) {
                float bv = f[0][bb];       int br = rbase;
                float v;
                v = f[0][2 + bb]; if (v > bv) { bv = v; br = rbase + 8;  }
                v = f[1][bb];     if (v > bv) { bv = v; br = rbase + 16; }
                v = f[1][2 + bb]; if (v > bv) { bv = v; br = rbase + 24; }
                unsigned long long p = pack_vi(bv, br);
                p = u64max(p, shfl_xor_u64(p, 4));
                p = u64max(p, shfl_xor_u64(p, 8));
                p = u64max(p, shfl_xor_u64(p, 16));
                if ((l >> 2) == 0)
                    atomicMax(&g_best[colb + ni * 8 + bb], p);
            }
        }
    }
}

__device__ __forceinline__ void flush_rows(int rowblk, int rloc, int l,
                                           float best[4], int bidx[4]) {
    #pragma unroll
    for (int bi = 0; bi < 4; bi++) {
        unsigned long long p = pack_vi(best[bi], bidx[bi]);
        p = u64max(p, shfl_xor_u64(p, 1));
        p = u64max(p, shfl_xor_u64(p, 2));
        if ((l & 3) == 0) {
            int row = rowblk * 128 + rloc + (bi >> 1) * 16 + (bi & 1) * 8;
            atomicMax(&g_best[row], p);
        }
        best[bi] = -2.0f; bidx[bi] = 0;
    }
}

__device__ __forceinline__ int free_slot(int sa, int sb) {
    if (sa != 0 && sb != 0) return 0;
    if (sa != 1 && sb != 1) return 1;
    return 2;
}

// ---------------------------------------------------------------------------
// Kernel 2: persistent balanced upper-tri GEMM-argmax. 152 CTAs, 512 thr,
// 16 warps (4x4 grid of 32x32 warp tiles); banked fp16 accumulators with
// previous-tile fold interleaved inside the k-loop.
__global__ void __launch_bounds__(NTHR, 1) koleo_gemm() {
    extern __shared__ __align__(16) char smem[];
    const uint32_t su = smem_u32(smem);
    const int tid = threadIdx.x;
    const int l   = tid & 31;
    const int wid = tid >> 5;
    const int wm  = wid >> 2;            // 0..3 (M)
    const int wn  = wid & 3;             // 0..3 (N)
    const int rloc = wm * 32 + (l >> 2);
    const int b   = blockIdx.x;

    // 2080 tiles = 152*13 + 104: first 104 CTAs take 14 tiles, rest 13.
    const int cnt = 13 + (b < 104 ? 1 : 0);
    int s = b * 13 + (b < 104 ? b : 104);
    int i = 0;
    while (s >= 64 - i) { s -= 64 - i; i++; }
    int j = i + s;

    const uint32_t aoff = (uint32_t)((wm * 32 + (l & 15)) * RSB + (l >> 4) * 16);
    const uint32_t boff = (uint32_t)((wn * 32 + (l & 7) + ((l >> 4) << 3)) * RSB +
                                     ((l >> 3) & 1) * 16);

    // initial loads (full tiles)
    int sa = 0, sb;
    #pragma unroll
    for (int q = 0; q < 8; q++) {
        int flat = tid + q * NTHR;
        int r = flat >> 5;
        int c = flat & 31;
        CP16(su + r * RSB + c * 16, g_xh + (size_t)i * 128 * DIM + (size_t)r * DIM + c * 8);
    }
    if (j != i) {
        #pragma unroll
        for (int q = 0; q < 8; q++) {
            int flat = tid + q * NTHR;
            int r = flat >> 5;
            int c = flat & 31;
            CP16(su + ATILE + r * RSB + c * 16,
                 g_xh + (size_t)j * 128 * DIM + (size_t)r * DIM + c * 8);
        }
        sb = 1;
    } else sb = 0;
    CPCOMMIT();

    float best[4] = {-2.0f, -2.0f, -2.0f, -2.0f};
    int   bidx[4] = {0, 0, 0, 0};
    uint32_t c0[2][4][2], c1[2][4][2];
    int pi = 0, pj = 0;

    #pragma unroll 1
    for (int n = 0; n < cnt; n++) {
        CPWAIT0();
        __syncthreads();

        int nsa = sa, nsb = sb, ii2 = i, jj2 = j;
        bool pf = (n + 1 < cnt);
        uint32_t pfdst = 0;
        const __half* pfsrc = nullptr;
        if (pf) {
            int fs = free_slot(sa, sb);
            pfdst = su + fs * ATILE;
            if (j + 1 < 64) {
                pfsrc = g_xh + (size_t)(j + 1) * 128 * DIM;
                nsb = fs; jj2 = j + 1;
            } else {
                pfsrc = g_xh + (size_t)(i + 1) * 128 * DIM;
                nsa = fs; nsb = fs; ii2 = i + 1; jj2 = i + 1;
            }
        }

        const bool dofold = (n > 0);
        const int  prbase = pi * 128 + rloc;
        const int  pcolb  = pj * 128 + wn * 32 + (l & 3) * 2;
        const bool pdiag  = (pi == pj);

        if ((n & 1) == 0)
            mma_tile_fold(c0, c1, su + sa * ATILE, su + sb * ATILE, aoff, boff,
                          pf, pfdst, pfsrc, tid, dofold, prbase, pcolb, pdiag,
                          l, best, bidx);
        else
            mma_tile_fold(c1, c0, su + sa * ATILE, su + sb * ATILE, aoff, boff,
                          pf, pfdst, pfsrc, tid, dofold, prbase, pcolb, pdiag,
                          l, best, bidx);
        if (pf) CPCOMMIT();
        if (dofold && pi != i)
            flush_rows(pi, rloc, l, best, bidx);

        pi = i; pj = j;
        sa = nsa; sb = nsb; i = ii2; j = jj2;
    }

    // fold + flush the final tile
    {
        const int  prbase = pi * 128 + rloc;
        const int  pcolb  = pj * 128 + wn * 32 + (l & 3) * 2;
        const bool pdiag  = (pi == pj);
        if (((cnt - 1) & 1) == 0)
            fold_tile(c0, prbase, pcolb, pdiag, l, best, bidx);
        else
            fold_tile(c1, prbase, pcolb, pdiag, l, best, bidx);
        flush_rows(pi, rloc, l, best, bidx);
    }
}

// ---------------------------------------------------------------------------
// Kernel 3: loss from stored dots. dist^2 = 2 - 2*dot for unit vectors;
// the winning dot is the high 32 bits of g_best (fp32 bits of dot+2).
// 16 blocks x 512 threads, one row per thread, block-reduced atomicAdd.
__global__ void koleo_loss(float* __restrict__ out) {
    __shared__ float sh[16];
    int gid  = blockIdx.x * 512 + threadIdx.x;
    int lane = threadIdx.x & 31;
    unsigned long long pb = g_best[gid];
    float dot = __uint_as_float((unsigned)(pb >> 32)) - 2.0f;
    float d2  = fmaxf(2.0f - 2.0f * dot, 0.0f);
    float s   = logf(sqrtf(d2) + kEPS);
    #pragma unroll
    for (int o = 16; o > 0; o >>= 1) s += __shfl_xor_sync(0xffffffffu, s, o);
    if (lane == 0) sh[threadIdx.x >> 5] = s;
    __syncthreads();
    if (threadIdx.x < 32) {
        float v = (threadIdx.x < 16) ? sh[threadIdx.x] : 0.0f;
        #pragma unroll
        for (int o = 8; o > 0; o >>= 1) v += __shfl_xor_sync(0xffffffffu, v, o);
        if (threadIdx.x == 0) atomicAdd(out, v * (-1.0f / (float)BROWS));
    }
}

// ---------------------------------------------------------------------------
extern "C" void kernel_launch(void* const* d_in, const int* in_sizes, int n_in,
                              void* d_out, int out_size) {
    const float* student = (const float*)d_in[0];
    float* out = (float*)d_out;
    (void)in_sizes; (void)n_in; (void)out_size;

    const int smem_bytes = 3 * ATILE;      // 202752 B dynamic
    cudaFuncSetAttribute(koleo_gemm, cudaFuncAttributeMaxDynamicSharedMemorySize, smem_bytes);

    koleo_normcvt<<<BROWS / 8, 256>>>(student, out);
    koleo_gemm<<<NCTA, NTHR, smem_bytes>>>();
    koleo_loss<<<BROWS / 512, 512>>>(out);
}